// round 1
// baseline (speedup 1.0000x reference)
#include <cuda_runtime.h>
#include <math.h>

#define NMAX 50000
#define EMAX 800000
#define DD 64
#define HH 4
#define HD 256
#define NEG_SLOPE 0.2f
#define BN_EPS 1e-5f

// ---------------- scratch (static device globals; no allocation) -------------
__device__ float    g_h[NMAX * HD];      // 51.2 MB: projected features [N, H*D]
__device__ float    g_asrc[NMAX * HH];
__device__ float    g_adst[NMAX * HH];
__device__ unsigned g_emax[NMAX * HH];   // monotone-encoded float max
__device__ float    g_denom[NMAX * HH];
__device__ double   g_sum[DD];
__device__ double   g_sumsq[DD];

// monotone order-preserving float<->uint encoding for atomicMax on floats
__device__ __forceinline__ unsigned f2u_mono(float f) {
    unsigned u = __float_as_uint(f);
    return (u & 0x80000000u) ? ~u : (u | 0x80000000u);
}
__device__ __forceinline__ float u2f_mono(unsigned x) {
    return __uint_as_float((x & 0x80000000u) ? (x ^ 0x80000000u) : ~x);
}
__device__ __forceinline__ float lrelu(float v) {
    return v >= 0.0f ? v : NEG_SLOPE * v;
}

// ---------------- kernel 0: zero-init -----------------------------------------
__global__ void zero_kernel(float* __restrict__ out, int nNodes) {
    int i = blockIdx.x * blockDim.x + threadIdx.x;
    if (i < nNodes * DD) out[i] = 0.0f;
    if (i < nNodes * HH) { g_denom[i] = 0.0f; g_emax[i] = 0u; }
    if (i < DD) { g_sum[i] = 0.0; g_sumsq[i] = 0.0; }
}

// ---------------- kernel 1: fused lin+PReLU then GAT projection ---------------
// Block: 256 threads, 64 nodes. Thread (jt = t&15, nt = t>>4) computes a 4x4
// register tile (4 nodes x 4 output channels, both strided by 16).
__global__ __launch_bounds__(256) void proj_kernel(
    const float* __restrict__ x, const float* __restrict__ Wlin,
    const float* __restrict__ blin, const float* __restrict__ prw,
    const float* __restrict__ Wgat, int nNodes)
{
    __shared__ float xs[64][65];
    __shared__ float ws[64][65];
    const int t  = threadIdx.x;
    const int n0 = blockIdx.x * 64;
    const int jt = t & 15;
    const int nt = t >> 4;

    // load x tile [64,64]
    for (int i = t; i < 4096; i += 256) {
        int n = i >> 6, d = i & 63;
        int gn = n0 + n;
        xs[n][d] = (gn < nNodes) ? x[gn * DD + d] : 0.0f;
    }
    // load W_lin [64,64] (row j = output channel)
    for (int i = t; i < 4096; i += 256) ws[i >> 6][i & 63] = Wlin[i];
    __syncthreads();

    // phase 1: x1 = PReLU(x @ Wlin^T + b)
    float acc[4][4];
#pragma unroll
    for (int a = 0; a < 4; a++)
#pragma unroll
        for (int b = 0; b < 4; b++) acc[a][b] = 0.0f;

#pragma unroll 8
    for (int k = 0; k < 64; k++) {
        float xv[4], wv[4];
#pragma unroll
        for (int a = 0; a < 4; a++) xv[a] = xs[nt + 16 * a][k];
#pragma unroll
        for (int b = 0; b < 4; b++) wv[b] = ws[jt + 16 * b][k];
#pragma unroll
        for (int a = 0; a < 4; a++)
#pragma unroll
            for (int b = 0; b < 4; b++) acc[a][b] += xv[a] * wv[b];
    }
    __syncthreads();   // all reads of xs done before overwrite

#pragma unroll
    for (int b = 0; b < 4; b++) {
        int j = jt + 16 * b;
        float bb = blin[j], pw = prw[j];
#pragma unroll
        for (int a = 0; a < 4; a++) {
            float v = acc[a][b] + bb;
            xs[nt + 16 * a][j] = (v >= 0.0f) ? v : pw * v;
        }
    }
    __syncthreads();

    // phase 2: h = x1 @ Wgat^T, 4 chunks of 64 output channels (== heads)
    for (int c = 0; c < 4; c++) {
        for (int i = t; i < 4096; i += 256) ws[i >> 6][i & 63] = Wgat[c * 4096 + i];
        __syncthreads();

        float a2[4][4];
#pragma unroll
        for (int a = 0; a < 4; a++)
#pragma unroll
            for (int b = 0; b < 4; b++) a2[a][b] = 0.0f;

#pragma unroll 8
        for (int k = 0; k < 64; k++) {
            float xv[4], wv[4];
#pragma unroll
            for (int a = 0; a < 4; a++) xv[a] = xs[nt + 16 * a][k];
#pragma unroll
            for (int b = 0; b < 4; b++) wv[b] = ws[jt + 16 * b][k];
#pragma unroll
            for (int a = 0; a < 4; a++)
#pragma unroll
                for (int b = 0; b < 4; b++) a2[a][b] += xv[a] * wv[b];
        }
        __syncthreads();   // done reading ws before next chunk overwrites

#pragma unroll
        for (int a = 0; a < 4; a++) {
            int gn = n0 + nt + 16 * a;
            if (gn < nNodes) {
#pragma unroll
                for (int b = 0; b < 4; b++)
                    g_h[gn * HD + c * 64 + jt + 16 * b] = a2[a][b];
            }
        }
    }
}

// ---------------- kernel 2: attention logits a_src/a_dst ----------------------
// warp per (node, head): dot(h[n,head,:], att_src[head,:]) etc.
__global__ void att_kernel(const float* __restrict__ att_src,
                           const float* __restrict__ att_dst, int nNodes)
{
    int warp = (blockIdx.x * blockDim.x + threadIdx.x) >> 5;
    int lane = threadIdx.x & 31;
    if (warp >= nNodes * HH) return;
    int n = warp >> 2, head = warp & 3;

    float2 v  = ((const float2*)(g_h + n * HD + head * 64))[lane];
    float2 as = ((const float2*)(att_src + head * 64))[lane];
    float2 ad = ((const float2*)(att_dst + head * 64))[lane];
    float ssrc = v.x * as.x + v.y * as.y;
    float sdst = v.x * ad.x + v.y * ad.y;
#pragma unroll
    for (int o = 16; o > 0; o >>= 1) {
        ssrc += __shfl_xor_sync(0xFFFFFFFFu, ssrc, o);
        sdst += __shfl_xor_sync(0xFFFFFFFFu, sdst, o);
    }
    if (lane == 0) {
        g_asrc[n * HH + head] = ssrc;
        g_adst[n * HH + head] = sdst;
    }
}

// ---------------- kernel 3: segment max of edge logits ------------------------
__global__ void emax_kernel(const int* __restrict__ ei, int E_, int M) {
    int i = blockIdx.x * blockDim.x + threadIdx.x;
    if (i >= M) return;
    int s, dn;
    if (i < E_) { s = ei[i]; dn = ei[E_ + i]; } else { s = dn = i - E_; }
    float4 as = *(const float4*)(g_asrc + s * 4);
    float4 ad = *(const float4*)(g_adst + dn * 4);
    atomicMax(&g_emax[dn * 4 + 0], f2u_mono(lrelu(as.x + ad.x)));
    atomicMax(&g_emax[dn * 4 + 1], f2u_mono(lrelu(as.y + ad.y)));
    atomicMax(&g_emax[dn * 4 + 2], f2u_mono(lrelu(as.z + ad.z)));
    atomicMax(&g_emax[dn * 4 + 3], f2u_mono(lrelu(as.w + ad.w)));
}

// ---------------- kernel 4: softmax denominators ------------------------------
__global__ void denom_kernel(const int* __restrict__ ei, int E_, int M) {
    int i = blockIdx.x * blockDim.x + threadIdx.x;
    if (i >= M) return;
    int s, dn;
    if (i < E_) { s = ei[i]; dn = ei[E_ + i]; } else { s = dn = i - E_; }
    float4 as = *(const float4*)(g_asrc + s * 4);
    float4 ad = *(const float4*)(g_adst + dn * 4);
    uint4  em = *(const uint4*)(g_emax + dn * 4);
    atomicAdd(&g_denom[dn * 4 + 0], __expf(lrelu(as.x + ad.x) - u2f_mono(em.x)));
    atomicAdd(&g_denom[dn * 4 + 1], __expf(lrelu(as.y + ad.y) - u2f_mono(em.y)));
    atomicAdd(&g_denom[dn * 4 + 2], __expf(lrelu(as.z + ad.z) - u2f_mono(em.z)));
    atomicAdd(&g_denom[dn * 4 + 3], __expf(lrelu(as.w + ad.w) - u2f_mono(em.w)));
}

// ---------------- kernel 5: weighted scatter (head-mean fused) ----------------
// warp per edge; lane covers d and d+32; 64 atomicAdds per edge (not 256).
__global__ void scatter_kernel(const int* __restrict__ ei, int E_, int M,
                               float* __restrict__ out)
{
    int warp = (blockIdx.x * blockDim.x + threadIdx.x) >> 5;
    int lane = threadIdx.x & 31;
    if (warp >= M) return;
    int s, dn;
    if (warp < E_) { s = ei[warp]; dn = ei[E_ + warp]; } else { s = dn = warp - E_; }

    float4 as = *(const float4*)(g_asrc + s * 4);
    float4 ad = *(const float4*)(g_adst + dn * 4);
    float4 dm = *(const float4*)(g_denom + dn * 4);
    uint4  em = *(const uint4*)(g_emax + dn * 4);

    float al0 = __expf(lrelu(as.x + ad.x) - u2f_mono(em.x)) / dm.x * 0.25f;
    float al1 = __expf(lrelu(as.y + ad.y) - u2f_mono(em.y)) / dm.y * 0.25f;
    float al2 = __expf(lrelu(as.z + ad.z) - u2f_mono(em.z)) / dm.z * 0.25f;
    float al3 = __expf(lrelu(as.w + ad.w) - u2f_mono(em.w)) / dm.w * 0.25f;

    const float* hp = g_h + s * HD;
#pragma unroll
    for (int r = 0; r < 2; r++) {
        int d = lane + 32 * r;
        float m = al0 * hp[d] + al1 * hp[64 + d] + al2 * hp[128 + d] + al3 * hp[192 + d];
        atomicAdd(&out[dn * DD + d], m);
    }
}

// ---------------- kernel 6: add bias, accumulate BN stats ---------------------
__global__ void stats_kernel(float* __restrict__ out,
                             const float* __restrict__ gbias, int nNodes)
{
    const int t = threadIdx.x;        // 256
    const int d = t & 63, r = t >> 6; // r in 0..3
    float s = 0.0f, sq = 0.0f;
    float bias = gbias[d];
    for (int n = blockIdx.x * 4 + r; n < nNodes; n += gridDim.x * 4) {
        float v = out[n * DD + d] + bias;
        out[n * DD + d] = v;
        s += v; sq += v * v;
    }
    __shared__ float sh[256], shq[256];
    sh[t] = s; shq[t] = sq;
    __syncthreads();
    if (r == 0) {
        s  = sh[d]  + sh[d + 64]  + sh[d + 128]  + sh[d + 192];
        sq = shq[d] + shq[d + 64] + shq[d + 128] + shq[d + 192];
        atomicAdd(&g_sum[d],   (double)s);
        atomicAdd(&g_sumsq[d], (double)sq);
    }
}

// ---------------- kernel 7: batchnorm + relu ----------------------------------
__global__ void bn_kernel(float* __restrict__ out, const float* __restrict__ gamma,
                          const float* __restrict__ beta, int nNodes, float invN)
{
    int i = blockIdx.x * blockDim.x + threadIdx.x;
    if (i >= nNodes * DD) return;
    int d = i & 63;
    float mean = (float)(g_sum[d] * (double)invN);
    float var  = (float)(g_sumsq[d] * (double)invN - (g_sum[d] * (double)invN) * (g_sum[d] * (double)invN));
    float scale = gamma[d] * rsqrtf(var + BN_EPS);
    float v = (out[i] - mean) * scale + beta[d];
    out[i] = v > 0.0f ? v : 0.0f;
}

// ---------------- launch -------------------------------------------------------
extern "C" void kernel_launch(void* const* d_in, const int* in_sizes, int n_in,
                              void* d_out, int out_size)
{
    const float* x       = (const float*)d_in[0];
    const int*   ei      = (const int*)  d_in[1];
    const float* Wlin    = (const float*)d_in[2];
    const float* blin    = (const float*)d_in[3];
    const float* prw     = (const float*)d_in[4];
    const float* Wgat    = (const float*)d_in[5];
    const float* att_src = (const float*)d_in[6];
    const float* att_dst = (const float*)d_in[7];
    const float* gbias   = (const float*)d_in[8];
    const float* gamma   = (const float*)d_in[9];
    const float* beta    = (const float*)d_in[10];
    float* out = (float*)d_out;

    const int Nn = in_sizes[0] / DD;
    const int Ee = in_sizes[1] / 2;
    const int M  = Ee + Nn;

    zero_kernel<<<(Nn * DD + 255) / 256, 256>>>(out, Nn);
    proj_kernel<<<(Nn + 63) / 64, 256>>>(x, Wlin, blin, prw, Wgat, Nn);
    att_kernel<<<(Nn * HH * 32 + 255) / 256, 256>>>(att_src, att_dst, Nn);
    emax_kernel<<<(M + 255) / 256, 256>>>(ei, Ee, M);
    denom_kernel<<<(M + 255) / 256, 256>>>(ei, Ee, M);
    {
        long long threads = (long long)M * 32;
        scatter_kernel<<<(int)((threads + 255) / 256), 256>>>(ei, Ee, M, out);
    }
    stats_kernel<<<128, 256>>>(out, gbias, Nn);
    bn_kernel<<<(Nn * DD + 255) / 256, 256>>>(out, gamma, beta, Nn, 1.0f / (float)Nn);
}

// round 2
// speedup vs baseline: 1.0833x; 1.0833x over previous
#include <cuda_runtime.h>
#include <math.h>

#define NMAX 50000
#define EMAX 800000
#define DD 64
#define HH 4
#define HD 256
#define NEG_SLOPE 0.2f
#define BN_EPS 1e-5f

// ---------------- scratch (static device globals; no allocation) -------------
__device__ float    g_h[NMAX * HD];      // 51.2 MB: projected features [N, H*D]
__device__ float    g_asrc[NMAX * HH];
__device__ float    g_adst[NMAX * HH];
__device__ int      g_deg[NMAX];
__device__ int      g_pos[NMAX];
__device__ int      g_off[NMAX + 1];
__device__ int      g_csr[EMAX];         // src node per dst-sorted edge
__device__ double   g_sum[DD];
__device__ double   g_sumsq[DD];

__device__ __forceinline__ float lrelu(float v) {
    return v >= 0.0f ? v : NEG_SLOPE * v;
}

// ---------------- kernel 0: init ----------------------------------------------
__global__ void init_kernel(int nNodes) {
    int i = blockIdx.x * blockDim.x + threadIdx.x;
    if (i < nNodes) { g_deg[i] = 0; g_pos[i] = 0; }
    if (i < DD) { g_sum[i] = 0.0; g_sumsq[i] = 0.0; }
}

// ---------------- kernel 1: fused lin+PReLU then GAT projection ---------------
__global__ __launch_bounds__(256) void proj_kernel(
    const float* __restrict__ x, const float* __restrict__ Wlin,
    const float* __restrict__ blin, const float* __restrict__ prw,
    const float* __restrict__ Wgat, int nNodes)
{
    __shared__ float xs[64][65];
    __shared__ float ws[64][65];
    const int t  = threadIdx.x;
    const int n0 = blockIdx.x * 64;
    const int jt = t & 15;
    const int nt = t >> 4;

    for (int i = t; i < 4096; i += 256) {
        int n = i >> 6, d = i & 63;
        int gn = n0 + n;
        xs[n][d] = (gn < nNodes) ? x[gn * DD + d] : 0.0f;
    }
    for (int i = t; i < 4096; i += 256) ws[i >> 6][i & 63] = Wlin[i];
    __syncthreads();

    float acc[4][4];
#pragma unroll
    for (int a = 0; a < 4; a++)
#pragma unroll
        for (int b = 0; b < 4; b++) acc[a][b] = 0.0f;

#pragma unroll 8
    for (int k = 0; k < 64; k++) {
        float xv[4], wv[4];
#pragma unroll
        for (int a = 0; a < 4; a++) xv[a] = xs[nt + 16 * a][k];
#pragma unroll
        for (int b = 0; b < 4; b++) wv[b] = ws[jt + 16 * b][k];
#pragma unroll
        for (int a = 0; a < 4; a++)
#pragma unroll
            for (int b = 0; b < 4; b++) acc[a][b] += xv[a] * wv[b];
    }
    __syncthreads();

#pragma unroll
    for (int b = 0; b < 4; b++) {
        int j = jt + 16 * b;
        float bb = blin[j], pw = prw[j];
#pragma unroll
        for (int a = 0; a < 4; a++) {
            float v = acc[a][b] + bb;
            xs[nt + 16 * a][j] = (v >= 0.0f) ? v : pw * v;
        }
    }
    __syncthreads();

    for (int c = 0; c < 4; c++) {
        for (int i = t; i < 4096; i += 256) ws[i >> 6][i & 63] = Wgat[c * 4096 + i];
        __syncthreads();

        float a2[4][4];
#pragma unroll
        for (int a = 0; a < 4; a++)
#pragma unroll
            for (int b = 0; b < 4; b++) a2[a][b] = 0.0f;

#pragma unroll 8
        for (int k = 0; k < 64; k++) {
            float xv[4], wv[4];
#pragma unroll
            for (int a = 0; a < 4; a++) xv[a] = xs[nt + 16 * a][k];
#pragma unroll
            for (int b = 0; b < 4; b++) wv[b] = ws[jt + 16 * b][k];
#pragma unroll
            for (int a = 0; a < 4; a++)
#pragma unroll
                for (int b = 0; b < 4; b++) a2[a][b] += xv[a] * wv[b];
        }
        __syncthreads();

#pragma unroll
        for (int a = 0; a < 4; a++) {
            int gn = n0 + nt + 16 * a;
            if (gn < nNodes) {
#pragma unroll
                for (int b = 0; b < 4; b++)
                    g_h[(size_t)gn * HD + c * 64 + jt + 16 * b] = a2[a][b];
            }
        }
    }
}

// ---------------- kernel 2: attention logits a_src/a_dst ----------------------
__global__ void att_kernel(const float* __restrict__ att_src,
                           const float* __restrict__ att_dst, int nNodes)
{
    int warp = (blockIdx.x * blockDim.x + threadIdx.x) >> 5;
    int lane = threadIdx.x & 31;
    if (warp >= nNodes * HH) return;
    int n = warp >> 2, head = warp & 3;

    float2 v  = ((const float2*)(g_h + (size_t)n * HD + head * 64))[lane];
    float2 as = ((const float2*)(att_src + head * 64))[lane];
    float2 ad = ((const float2*)(att_dst + head * 64))[lane];
    float ssrc = v.x * as.x + v.y * as.y;
    float sdst = v.x * ad.x + v.y * ad.y;
#pragma unroll
    for (int o = 16; o > 0; o >>= 1) {
        ssrc += __shfl_xor_sync(0xFFFFFFFFu, ssrc, o);
        sdst += __shfl_xor_sync(0xFFFFFFFFu, sdst, o);
    }
    if (lane == 0) {
        g_asrc[n * HH + head] = ssrc;
        g_adst[n * HH + head] = sdst;
    }
}

// ---------------- kernel 3: degree histogram ----------------------------------
__global__ void hist_kernel(const int* __restrict__ ei, int E_) {
    int i = blockIdx.x * blockDim.x + threadIdx.x;
    if (i < E_) atomicAdd(&g_deg[ei[E_ + i]], 1);
}

// ---------------- kernel 4: exclusive scan (single block) ---------------------
__global__ __launch_bounds__(1024) void scan_kernel(int nNodes) {
    __shared__ int sh[1024];
    const int t = threadIdx.x;
    const int chunk = (nNodes + 1023) / 1024;
    const int b = t * chunk;
    const int e = min(b + chunk, nNodes);
    int s = 0;
    for (int i = b; i < e; i++) s += g_deg[i];
    sh[t] = s;
    __syncthreads();
    for (int o = 1; o < 1024; o <<= 1) {
        int v = 0;
        if (t >= o) v = sh[t - o];
        __syncthreads();
        if (t >= o) sh[t] += v;
        __syncthreads();
    }
    int off = (t > 0) ? sh[t - 1] : 0;
    for (int i = b; i < e; i++) { g_off[i] = off; off += g_deg[i]; }
    if (t == 1023) g_off[nNodes] = sh[1023];
}

// ---------------- kernel 5: fill CSR ------------------------------------------
__global__ void fill_kernel(const int* __restrict__ ei, int E_) {
    int i = blockIdx.x * blockDim.x + threadIdx.x;
    if (i >= E_) return;
    int s = ei[i], dn = ei[E_ + i];
    int p = atomicAdd(&g_pos[dn], 1);
    g_csr[g_off[dn] + p] = s;
}

// ---------------- kernel 6: fused softmax + gather aggregate ------------------
// one warp per destination node. Online softmax over incident edges + self loop,
// then weighted gather of h rows with head-mean fused. No atomics.
__global__ __launch_bounds__(256) void agg_kernel(
    const float* __restrict__ gbias, float* __restrict__ out, int nNodes)
{
    const int warp = (blockIdx.x * blockDim.x + threadIdx.x) >> 5;
    const int lane = threadIdx.x & 31;
    if (warp >= nNodes) return;
    const int n = warp;
    const int beg = g_off[n], end = g_off[n + 1];

    const float4 ad = *(const float4*)(g_adst + n * 4);

    // --- phase 1: online softmax (max & sum) per head, lanes strided over edges
    float m0 = -1e30f, m1 = -1e30f, m2 = -1e30f, m3 = -1e30f;
    float s0 = 0.f, s1 = 0.f, s2 = 0.f, s3 = 0.f;
    for (int i = beg + lane; i < end; i += 32) {
        int s = g_csr[i];
        float4 as = *(const float4*)(g_asrc + s * 4);
        float l0 = lrelu(as.x + ad.x), l1 = lrelu(as.y + ad.y);
        float l2 = lrelu(as.z + ad.z), l3 = lrelu(as.w + ad.w);
        float nm;
        nm = fmaxf(m0, l0); s0 = s0 * __expf(m0 - nm) + __expf(l0 - nm); m0 = nm;
        nm = fmaxf(m1, l1); s1 = s1 * __expf(m1 - nm) + __expf(l1 - nm); m1 = nm;
        nm = fmaxf(m2, l2); s2 = s2 * __expf(m2 - nm) + __expf(l2 - nm); m2 = nm;
        nm = fmaxf(m3, l3); s3 = s3 * __expf(m3 - nm) + __expf(l3 - nm); m3 = nm;
    }
#pragma unroll
    for (int o = 16; o > 0; o >>= 1) {
        float om, os, nm;
        om = __shfl_xor_sync(~0u, m0, o); os = __shfl_xor_sync(~0u, s0, o);
        nm = fmaxf(m0, om); s0 = s0 * __expf(m0 - nm) + os * __expf(om - nm); m0 = nm;
        om = __shfl_xor_sync(~0u, m1, o); os = __shfl_xor_sync(~0u, s1, o);
        nm = fmaxf(m1, om); s1 = s1 * __expf(m1 - nm) + os * __expf(om - nm); m1 = nm;
        om = __shfl_xor_sync(~0u, m2, o); os = __shfl_xor_sync(~0u, s2, o);
        nm = fmaxf(m2, om); s2 = s2 * __expf(m2 - nm) + os * __expf(om - nm); m2 = nm;
        om = __shfl_xor_sync(~0u, m3, o); os = __shfl_xor_sync(~0u, s3, o);
        nm = fmaxf(m3, om); s3 = s3 * __expf(m3 - nm) + os * __expf(om - nm); m3 = nm;
    }
    // self-loop logit (src = dst = n); merge into max/sum
    const float4 asn = *(const float4*)(g_asrc + n * 4);
    const float ls0 = lrelu(asn.x + ad.x), ls1 = lrelu(asn.y + ad.y);
    const float ls2 = lrelu(asn.z + ad.z), ls3 = lrelu(asn.w + ad.w);
    {
        float nm;
        nm = fmaxf(m0, ls0); s0 = s0 * __expf(m0 - nm) + __expf(ls0 - nm); m0 = nm;
        nm = fmaxf(m1, ls1); s1 = s1 * __expf(m1 - nm) + __expf(ls1 - nm); m1 = nm;
        nm = fmaxf(m2, ls2); s2 = s2 * __expf(m2 - nm) + __expf(ls2 - nm); m2 = nm;
        nm = fmaxf(m3, ls3); s3 = s3 * __expf(m3 - nm) + __expf(ls3 - nm); m3 = nm;
    }
    const float i0 = 0.25f / s0, i1 = 0.25f / s1, i2 = 0.25f / s2, i3 = 0.25f / s3;

    // --- phase 2: weighted gather-accumulate; lane covers d = 2*lane, 2*lane+1
    float ax = 0.f, ay = 0.f;
    {   // self contribution
        float w0 = __expf(ls0 - m0) * i0, w1 = __expf(ls1 - m1) * i1;
        float w2 = __expf(ls2 - m2) * i2, w3 = __expf(ls3 - m3) * i3;
        const float2* hp = (const float2*)(g_h + (size_t)n * HD);
        float2 v0 = hp[lane], v1 = hp[32 + lane], v2 = hp[64 + lane], v3 = hp[96 + lane];
        ax += w0 * v0.x + w1 * v1.x + w2 * v2.x + w3 * v3.x;
        ay += w0 * v0.y + w1 * v1.y + w2 * v2.y + w3 * v3.y;
    }
    for (int base = beg; base < end; base += 32) {
        int rem = end - base;
        int sl = 0;
        float a0 = 0.f, a1 = 0.f, a2 = 0.f, a3 = 0.f;
        if (lane < rem) {
            sl = g_csr[base + lane];
            float4 as = *(const float4*)(g_asrc + sl * 4);
            a0 = __expf(lrelu(as.x + ad.x) - m0) * i0;
            a1 = __expf(lrelu(as.y + ad.y) - m1) * i1;
            a2 = __expf(lrelu(as.z + ad.z) - m2) * i2;
            a3 = __expf(lrelu(as.w + ad.w) - m3) * i3;
        }
        int cnt = min(32, rem);
        for (int j = 0; j < cnt; j++) {
            int s  = __shfl_sync(~0u, sl, j);
            float w0 = __shfl_sync(~0u, a0, j);
            float w1 = __shfl_sync(~0u, a1, j);
            float w2 = __shfl_sync(~0u, a2, j);
            float w3 = __shfl_sync(~0u, a3, j);
            const float2* hp = (const float2*)(g_h + (size_t)s * HD);
            float2 v0 = hp[lane], v1 = hp[32 + lane], v2 = hp[64 + lane], v3 = hp[96 + lane];
            ax += w0 * v0.x + w1 * v1.x + w2 * v2.x + w3 * v3.x;
            ay += w0 * v0.y + w1 * v1.y + w2 * v2.y + w3 * v3.y;
        }
    }
    float2 bias = ((const float2*)gbias)[lane];
    ((float2*)(out + (size_t)n * DD))[lane] = make_float2(ax + bias.x, ay + bias.y);
}

// ---------------- kernel 7: BN stats (read-only) ------------------------------
__global__ void stats_kernel(const float* __restrict__ out, int nNodes)
{
    const int t = threadIdx.x;        // 256
    const int d = t & 63, r = t >> 6;
    float s = 0.0f, sq = 0.0f;
    for (int n = blockIdx.x * 4 + r; n < nNodes; n += gridDim.x * 4) {
        float v = out[(size_t)n * DD + d];
        s += v; sq += v * v;
    }
    __shared__ float sh[256], shq[256];
    sh[t] = s; shq[t] = sq;
    __syncthreads();
    if (r == 0) {
        s  = sh[d]  + sh[d + 64]  + sh[d + 128]  + sh[d + 192];
        sq = shq[d] + shq[d + 64] + shq[d + 128] + shq[d + 192];
        atomicAdd(&g_sum[d],   (double)s);
        atomicAdd(&g_sumsq[d], (double)sq);
    }
}

// ---------------- kernel 8: batchnorm + relu ----------------------------------
__global__ void bn_kernel(float* __restrict__ out, const float* __restrict__ gamma,
                          const float* __restrict__ beta, int nNodes, float invN)
{
    int i = blockIdx.x * blockDim.x + threadIdx.x;
    if (i >= nNodes * DD) return;
    int d = i & 63;
    double mean_d = g_sum[d] * (double)invN;
    float mean = (float)mean_d;
    float var  = (float)(g_sumsq[d] * (double)invN - mean_d * mean_d);
    float scale = gamma[d] * rsqrtf(var + BN_EPS);
    float v = (out[i] - mean) * scale + beta[d];
    out[i] = v > 0.0f ? v : 0.0f;
}

// ---------------- launch -------------------------------------------------------
extern "C" void kernel_launch(void* const* d_in, const int* in_sizes, int n_in,
                              void* d_out, int out_size)
{
    const float* x       = (const float*)d_in[0];
    const int*   ei      = (const int*)  d_in[1];
    const float* Wlin    = (const float*)d_in[2];
    const float* blin    = (const float*)d_in[3];
    const float* prw     = (const float*)d_in[4];
    const float* Wgat    = (const float*)d_in[5];
    const float* att_src = (const float*)d_in[6];
    const float* att_dst = (const float*)d_in[7];
    const float* gbias   = (const float*)d_in[8];
    const float* gamma   = (const float*)d_in[9];
    const float* beta    = (const float*)d_in[10];
    float* out = (float*)d_out;

    const int Nn = in_sizes[0] / DD;
    const int Ee = in_sizes[1] / 2;

    init_kernel<<<(Nn + 255) / 256, 256>>>(Nn);
    proj_kernel<<<(Nn + 63) / 64, 256>>>(x, Wlin, blin, prw, Wgat, Nn);
    att_kernel<<<(Nn * HH * 32 + 255) / 256, 256>>>(att_src, att_dst, Nn);
    hist_kernel<<<(Ee + 255) / 256, 256>>>(ei, Ee);
    scan_kernel<<<1, 1024>>>(Nn);
    fill_kernel<<<(Ee + 255) / 256, 256>>>(ei, Ee);
    {
        long long threads = (long long)Nn * 32;
        agg_kernel<<<(int)((threads + 255) / 256), 256>>>(gbias, out, Nn);
    }
    stats_kernel<<<128, 256>>>(out, Nn);
    bn_kernel<<<(Nn * DD + 255) / 256, 256>>>(out, gamma, beta, Nn, 1.0f / (float)Nn);
}